// round 1
// baseline (speedup 1.0000x reference)
#include <cuda_runtime.h>
#include <math.h>

// Scratch for E = exp(x @ W^T), 256x512 fp32 (allocation-free per harness rules)
__device__ float g_E[256 * 512];

constexpr int BM = 32, BN = 32, BK = 32;

// GEMM1 (NT): E[m,n] = expf( sum_k X[m,k] * W[n,k] )
// M=256, N=512, K=1024. X row-major (K contig), W row-major (K contig).
__global__ __launch_bounds__(256) void gemm1_exp_kernel(
    const float* __restrict__ X, const float* __restrict__ W)
{
    __shared__ float As[BM][BK + 1];
    __shared__ float Bs[BN][BK + 1];

    const int tid = threadIdx.x;
    const int m0 = blockIdx.y * BM;
    const int n0 = blockIdx.x * BN;

    // compute mapping: 16x16 thread grid, each thread a 2x2 micro-tile
    const int tr = tid >> 4;      // 0..15
    const int tc = tid & 15;      // 0..15
    // load mapping: 32 rows, 8 float4 per row
    const int lr = tid >> 3;            // 0..31
    const int lc = (tid & 7) << 2;      // 0,4,...,28

    float acc00 = 0.f, acc01 = 0.f, acc10 = 0.f, acc11 = 0.f;

    for (int k0 = 0; k0 < 1024; k0 += BK) {
        float4 a = *(const float4*)(X + (m0 + lr) * 1024 + k0 + lc);
        As[lr][lc + 0] = a.x; As[lr][lc + 1] = a.y;
        As[lr][lc + 2] = a.z; As[lr][lc + 3] = a.w;
        float4 b = *(const float4*)(W + (n0 + lr) * 1024 + k0 + lc);
        Bs[lr][lc + 0] = b.x; Bs[lr][lc + 1] = b.y;
        Bs[lr][lc + 2] = b.z; Bs[lr][lc + 3] = b.w;
        __syncthreads();

        #pragma unroll
        for (int k = 0; k < BK; k++) {
            float a0 = As[2 * tr][k];
            float a1 = As[2 * tr + 1][k];
            float b0 = Bs[2 * tc][k];
            float b1 = Bs[2 * tc + 1][k];
            acc00 += a0 * b0; acc01 += a0 * b1;
            acc10 += a1 * b0; acc11 += a1 * b1;
        }
        __syncthreads();
    }

    const int m = m0 + 2 * tr;
    const int n = n0 + 2 * tc;
    g_E[m * 512 + n]           = expf(acc00);
    g_E[m * 512 + n + 1]       = expf(acc01);
    g_E[(m + 1) * 512 + n]     = expf(acc10);
    g_E[(m + 1) * 512 + n + 1] = expf(acc11);
}

// GEMM2 (NN): Y[m,n] = sum_k E[m,k] * expf(U[k,n]) + 512
// M=256, N=1024, K=512. E row-major (K contig), U row-major (N contig).
__global__ __launch_bounds__(256) void gemm2_kernel(
    const float* __restrict__ U, float* __restrict__ Y)
{
    __shared__ float As[BM][BK + 1];   // E tile, (m, k)
    __shared__ float Bs[BK][BN];       // exp(U) tile, (k, n)

    const int tid = threadIdx.x;
    const int m0 = blockIdx.y * BM;
    const int n0 = blockIdx.x * BN;

    const int tr = tid >> 4;
    const int tc = tid & 15;
    const int lr = tid >> 3;
    const int lc = (tid & 7) << 2;

    float acc00 = 0.f, acc01 = 0.f, acc10 = 0.f, acc11 = 0.f;

    for (int k0 = 0; k0 < 512; k0 += BK) {
        float4 a = *(const float4*)(g_E + (m0 + lr) * 512 + k0 + lc);
        As[lr][lc + 0] = a.x; As[lr][lc + 1] = a.y;
        As[lr][lc + 2] = a.z; As[lr][lc + 3] = a.w;

        float4 b = *(const float4*)(U + (k0 + lr) * 1024 + n0 + lc);
        float4 be;
        be.x = expf(b.x); be.y = expf(b.y);
        be.z = expf(b.z); be.w = expf(b.w);
        *(float4*)&Bs[lr][lc] = be;
        __syncthreads();

        #pragma unroll
        for (int k = 0; k < BK; k++) {
            float a0 = As[2 * tr][k];
            float a1 = As[2 * tr + 1][k];
            float b0 = Bs[k][2 * tc];
            float b1 = Bs[k][2 * tc + 1];
            acc00 += a0 * b0; acc01 += a0 * b1;
            acc10 += a1 * b0; acc11 += a1 * b1;
        }
        __syncthreads();
    }

    const int m = m0 + 2 * tr;
    const int n = n0 + 2 * tc;
    Y[m * 1024 + n]           = acc00 + 512.0f;
    Y[m * 1024 + n + 1]       = acc01 + 512.0f;
    Y[(m + 1) * 1024 + n]     = acc10 + 512.0f;
    Y[(m + 1) * 1024 + n + 1] = acc11 + 512.0f;
}

extern "C" void kernel_launch(void* const* d_in, const int* in_sizes, int n_in,
                              void* d_out, int out_size)
{
    const float* x = (const float*)d_in[0];   // 256 x 1024
    const float* W = (const float*)d_in[1];   // 512 x 1024
    const float* u = (const float*)d_in[2];   // 512 x 1024
    float* y = (float*)d_out;                 // 256 x 1024

    // GEMM1: E = exp(x @ W^T), grid: N-tiles x M-tiles = 16 x 8 = 128 blocks
    gemm1_exp_kernel<<<dim3(512 / BN, 256 / BM), 256>>>(x, W);
    // GEMM2: y = E @ exp(u) + 512, grid: 32 x 8 = 256 blocks
    gemm2_kernel<<<dim3(1024 / BN, 256 / BM), 256>>>(u, y);
}